// round 10
// baseline (speedup 1.0000x reference)
#include <cuda_runtime.h>
#include <cuda_bf16.h>
#include <cstdint>

// Correlation1D band-GEMM: k16 bf16 3-pass fp32 emulation.
// R10: staging buffers deleted. Both inputs are prefetched into REGISTERS
// (coalesced __ldcg) one chunk ahead; B is converted straight into the
// double-buffered bf16 tile; A fragments are built in registers.
// One __syncthreads per 16-channel chunk.
// out[b,d,h,w] = (1/256)*sum_c in1[b,c,h,w]*in2pad[b,c,h,w+d-40]

#define Bn 8
#define Cn 256
#define Hn 96
#define Wn 192
#define Dn 81
#define PADn 40
#define HWn (Hn * Wn)

#define NTHREADS 384
#define KC 16
#define NCHUNK (Cn / KC)          // 16
#define BROWS 272

#define ROWB 64                   // tileB row: [hi 16ch = 32B | lo 32B]
#define TBB (BROWS * ROWB)        // 17408
#define DYNSMEM 63232             // max(2*TBB=34816, outT 81*192*4=62208)+align

#define SWX(row, koff) ((unsigned)(koff) ^ ((((unsigned)(row) >> 1) & 3u) << 4))

static __device__ __forceinline__ uint32_t smem_u32(const void* p) {
    uint32_t a;
    asm("{ .reg .u64 t; cvta.to.shared.u64 t, %1; cvt.u32.u64 %0, t; }" : "=r"(a) : "l"(p));
    return a;
}

#define MMA_BF16(a4, A, b0, b1)                                                \
    asm volatile("mma.sync.aligned.m16n8k16.row.col.f32.bf16.bf16.f32 "        \
        "{%0,%1,%2,%3}, {%4,%5,%6,%7}, {%8,%9}, {%0,%1,%2,%3};"                \
        : "+f"((a4)[0]), "+f"((a4)[1]), "+f"((a4)[2]), "+f"((a4)[3])           \
        : "r"((A)[0]), "r"((A)[1]), "r"((A)[2]), "r"((A)[3]), "r"(b0), "r"(b1))

#define LDSM_X4(r, addr)                                                       \
    asm volatile("ldmatrix.sync.aligned.m8n8.x4.shared.b16 {%0,%1,%2,%3}, [%4];" \
        : "=r"((r)[0]), "=r"((r)[1]), "=r"((r)[2]), "=r"((r)[3]) : "r"(addr))

__global__ __launch_bounds__(NTHREADS, 2)
void corr1d_rp_kernel(const float* __restrict__ in1,
                      const float* __restrict__ in2,
                      float* __restrict__ out) {
    extern __shared__ char dsm_raw[];
    const uint32_t dsm_addr = smem_u32(dsm_raw);
    const uint32_t base_u = (dsm_addr + 1023u) & ~1023u;
    char* smp = dsm_raw + (base_u - dsm_addr);

    const int h = blockIdx.x;
    const int b = blockIdx.y;
    const int tid = threadIdx.x;
    const int wid = tid >> 5;
    const int lane = tid & 31;

    // ---- B-convert role: thread t handles column cv_col, channel group cv_g ----
    const int cv_col = tid % 192;          // global w' column (always valid)
    const int cv_g = tid / 192;            // 0: ch 0-7, 1: ch 8-15
    const int cv_u = cv_col + PADn;        // tile row
    const float* bsrc = in2 + (size_t)b * Cn * HWn + (size_t)h * Wn + cv_col
                        + (size_t)(8 * cv_g) * HWn;

    // ---- compute role constants ----
    const int w0 = wid * 16;
    const int b_rowoff = (lane & 7) + ((lane >> 4) & 1) * 8;
    const int b_k16 = ((lane >> 3) & 1) * 16;
    const int ad_w = w0 + (lane >> 2);
    const int ad_k = (lane & 3) * 2;
    const float* asrc = in1 + (size_t)b * Cn * HWn + (size_t)h * Wn;

    // ---- zero tileB pad rows (u<40, u>=232) in both buffers, once ----
    for (int t = tid; t < 2 * 80 * 4; t += NTHREADS) {
        const int buf = t / 320;
        const int r = (t % 320) / 4;
        const int j = t % 4;
        const int u = (r < 40) ? r : (232 + r - 40);
        ((uint4*)(smp + buf * TBB + u * ROWB))[j] = make_uint4(0, 0, 0, 0);
    }

    float acc[12][4];
#pragma unroll
    for (int n = 0; n < 12; ++n)
#pragma unroll
        for (int i = 0; i < 4; ++i) acc[n][i] = 0.0f;

    float pfA[8], pfB[8];
    uint32_t AH[4], AL[4];

    // prefetch chunk ch into pfA/pfB
    auto loadc = [&](int ch) {
        const size_t co = (size_t)ch * KC * HWn;
#pragma unroll
        for (int q = 0; q < 4; ++q) {
            const int kk = ad_k + (q >> 1) * 8;
            const int ww = ad_w + (q & 1) * 8;
            pfA[2 * q] = __ldcg(asrc + co + (size_t)kk * HWn + ww);
            pfA[2 * q + 1] = __ldcg(asrc + co + (size_t)(kk + 1) * HWn + ww);
        }
#pragma unroll
        for (int j = 0; j < 8; ++j)
            pfB[j] = __ldcg(bsrc + co + (size_t)j * HWn);
    };

    loadc(0);

    for (int i = 0; i < NCHUNK; ++i) {
        // ---- compute chunk i-1 from tileB[(i-1)&1] with AH/AL from last iter ----
        if (i > 0) {
            const uint32_t tb = base_u + ((i - 1) & 1) * TBB;
#pragma unroll
            for (int ntp = 0; ntp < 6; ++ntp) {
                const int ub = w0 + ntp * 16 + b_rowoff;
                uint32_t bh[4], bl[4];
                LDSM_X4(bh, tb + ub * ROWB + SWX(ub, b_k16));
                LDSM_X4(bl, tb + ub * ROWB + SWX(ub, 32 + b_k16));
#pragma unroll
                for (int t2 = 0; t2 < 2; ++t2) {
                    float* a4 = acc[ntp * 2 + t2];
                    MMA_BF16(a4, AH, bh[2 * t2], bh[2 * t2 + 1]);
                    MMA_BF16(a4, AH, bl[2 * t2], bl[2 * t2 + 1]);
                    MMA_BF16(a4, AL, bh[2 * t2], bh[2 * t2 + 1]);
                }
            }
        }

        // ---- build A fragments for chunk i from pfA (registers) ----
#pragma unroll
        for (int q = 0; q < 4; ++q) {
            const float f0 = pfA[2 * q];
            const float f1 = pfA[2 * q + 1];
            __nv_bfloat162 hh = __floats2bfloat162_rn(f0, f1);
            const float r0 = f0 - __bfloat162float(hh.x);
            const float r1 = f1 - __bfloat162float(hh.y);
            __nv_bfloat162 ll = __floats2bfloat162_rn(r0, r1);
            AH[q] = *(uint32_t*)&hh;
            AL[q] = *(uint32_t*)&ll;
        }

        // ---- convert B chunk i from pfB -> tileB[i&1] ----
        {
            unsigned hu[4], lu[4];
#pragma unroll
            for (int k = 0; k < 4; ++k) {
                __nv_bfloat162 hh = __floats2bfloat162_rn(pfB[2 * k], pfB[2 * k + 1]);
                const float r0 = pfB[2 * k] - __bfloat162float(hh.x);
                const float r1 = pfB[2 * k + 1] - __bfloat162float(hh.y);
                __nv_bfloat162 ll = __floats2bfloat162_rn(r0, r1);
                hu[k] = *(unsigned*)&hh;
                lu[k] = *(unsigned*)&ll;
            }
            char* rowp = smp + (i & 1) * TBB + cv_u * ROWB;
            *(uint4*)(rowp + SWX(cv_u, 16 * cv_g)) = make_uint4(hu[0], hu[1], hu[2], hu[3]);
            *(uint4*)(rowp + SWX(cv_u, 32 + 16 * cv_g)) = make_uint4(lu[0], lu[1], lu[2], lu[3]);
        }

        // ---- prefetch chunk i+1 (lands during compute(i) next iter) ----
        if (i + 1 < NCHUNK) loadc(i + 1);

        __syncthreads();   // tileB[i&1] complete; safe for next iter's compute
    }

    // ---- tail: compute chunk NCHUNK-1 ----
    {
        const uint32_t tb = base_u + ((NCHUNK - 1) & 1) * TBB;
#pragma unroll
        for (int ntp = 0; ntp < 6; ++ntp) {
            const int ub = w0 + ntp * 16 + b_rowoff;
            uint32_t bh[4], bl[4];
            LDSM_X4(bh, tb + ub * ROWB + SWX(ub, b_k16));
            LDSM_X4(bl, tb + ub * ROWB + SWX(ub, 32 + b_k16));
#pragma unroll
            for (int t2 = 0; t2 < 2; ++t2) {
                float* a4 = acc[ntp * 2 + t2];
                MMA_BF16(a4, AH, bh[2 * t2], bh[2 * t2 + 1]);
                MMA_BF16(a4, AH, bl[2 * t2], bl[2 * t2 + 1]);
                MMA_BF16(a4, AL, bh[2 * t2], bh[2 * t2 + 1]);
            }
        }
    }
    __syncthreads();

    // ---- epilogue: band extraction into smem, then coalesced store ----
    float* outT = (float*)smp;  // [81][192] f32
    const float scale = 1.0f / (float)Cn;
    const int r_ = lane >> 2;
    const int col2 = (lane & 3) * 2;
#pragma unroll
    for (int nt = 0; nt < 12; ++nt) {
#pragma unroll
        for (int half = 0; half < 2; ++half) {
            const int mrow = r_ + half * 8;
            const int w = w0 + mrow;
#pragma unroll
            for (int e = 0; e < 2; ++e) {
                const int d = nt * 8 + col2 + e - mrow;
                if (d >= 0 && d < Dn) {
                    outT[d * Wn + w] = acc[nt][half * 2 + e] * scale;
                }
            }
        }
    }
    __syncthreads();

    for (int t = tid; t < Dn * (Wn / 4); t += NTHREADS) {
        const int d = t / (Wn / 4);
        const int q = t % (Wn / 4);
        const float4 v = ((const float4*)outT)[d * (Wn / 4) + q];
        *(float4*)(out + (((size_t)b * Dn + d) * Hn + h) * Wn + q * 4) = v;
    }
}

extern "C" void kernel_launch(void* const* d_in, const int* in_sizes, int n_in,
                              void* d_out, int out_size) {
    const float* in1 = (const float*)d_in[0];
    const float* in2 = (const float*)d_in[1];
    float* out = (float*)d_out;
    cudaFuncSetAttribute(corr1d_rp_kernel, cudaFuncAttributeMaxDynamicSharedMemorySize, DYNSMEM);
    dim3 grid(Hn, Bn);   // (96, 8)
    corr1d_rp_kernel<<<grid, NTHREADS, DYNSMEM>>>(in1, in2, out);
}

// round 11
// speedup vs baseline: 1.1516x; 1.1516x over previous
#include <cuda_runtime.h>
#include <cuda_bf16.h>
#include <cstdint>

// Correlation1D band-GEMM: k16 bf16 3-pass fp32 emulation.
// R11 = R9 (3-slot cp.async ring, A-direct, 1 sync/chunk) with m32 per warp:
// 6 warps x 192 threads; each warp computes a 32-row m-window sharing one set
// of B fragments across its two m16 tiles -> B LDSM traffic cut 74KB->43KB/chunk.
// out[b,d,h,w] = (1/256)*sum_c in1[b,c,h,w]*in2pad[b,c,h,w+d-40]

#define Bn 8
#define Cn 256
#define Hn 96
#define Wn 192
#define Dn 81
#define PADn 40
#define HWn (Hn * Wn)

#define NTHREADS 192
#define NWARPS 6
#define KC 16
#define NCHUNK (Cn / KC)          // 16
#define BROWS 272

#define STROWF 196                // fp32 stage row floats (192 used, pad for banks)
#define STBYTES (KC * STROWF * 4) // 12544
#define STPAIR (2 * STBYTES)      // 25088 (A stage + B stage per ring slot)

#define ROWB 64                   // tileB row: [hi 16ch = 32B | lo 32B]
#define TBB (BROWS * ROWB)        // 17408

#define OFF_TB0 (3 * STPAIR)                // 75264
#define OFF_TB1 (OFF_TB0 + TBB)             // 92672
#define SMEM_USED (OFF_TB1 + TBB)           // 110080
#define DYNSMEM (SMEM_USED + 1024)

#define SWX(row, koff) ((unsigned)(koff) ^ ((((unsigned)(row) >> 1) & 3u) << 4))

static __device__ __forceinline__ uint32_t smem_u32(const void* p) {
    uint32_t a;
    asm("{ .reg .u64 t; cvta.to.shared.u64 t, %1; cvt.u32.u64 %0, t; }" : "=r"(a) : "l"(p));
    return a;
}

static __device__ __forceinline__ void cp_async16(uint32_t dst, const void* src) {
    asm volatile("cp.async.cg.shared.global [%0], [%1], 16;" :: "r"(dst), "l"(src) : "memory");
}

#define MMA_BF16(a4, A, b0, b1)                                                \
    asm volatile("mma.sync.aligned.m16n8k16.row.col.f32.bf16.bf16.f32 "        \
        "{%0,%1,%2,%3}, {%4,%5,%6,%7}, {%8,%9}, {%0,%1,%2,%3};"                \
        : "+f"((a4)[0]), "+f"((a4)[1]), "+f"((a4)[2]), "+f"((a4)[3])           \
        : "r"((A)[0]), "r"((A)[1]), "r"((A)[2]), "r"((A)[3]), "r"(b0), "r"(b1))

#define LDSM_X4(r, addr)                                                       \
    asm volatile("ldmatrix.sync.aligned.m8n8.x4.shared.b16 {%0,%1,%2,%3}, [%4];" \
        : "=r"((r)[0]), "=r"((r)[1]), "=r"((r)[2]), "=r"((r)[3]) : "r"(addr))

__global__ __launch_bounds__(NTHREADS, 2)
void corr1d_m32_kernel(const float* __restrict__ in1,
                       const float* __restrict__ in2,
                       float* __restrict__ out) {
    extern __shared__ char dsm_raw[];
    const uint32_t dsm_addr = smem_u32(dsm_raw);
    const uint32_t base_u = (dsm_addr + 1023u) & ~1023u;
    char* smp = dsm_raw + (base_u - dsm_addr);

    const int h = blockIdx.x;
    const int b = blockIdx.y;
    const int tid = threadIdx.x;
    const int wid = tid >> 5;
    const int lane = tid & 31;

    const float* a_src = in1 + (size_t)b * Cn * HWn + (size_t)h * Wn;
    const float* b_src = in2 + (size_t)b * Cn * HWn + (size_t)h * Wn;

    // ---- zero tileB pad rows (u<40, u>=232) in both buffers, once ----
    for (int t = tid; t < 2 * 80 * 4; t += NTHREADS) {
        const int buf = t / 320;
        const int r = (t % 320) / 4;
        const int j = t % 4;
        const int u = (r < 40) ? r : (232 + r - 40);
        ((uint4*)(smp + (buf ? OFF_TB1 : OFF_TB0) + u * ROWB))[j] = make_uint4(0, 0, 0, 0);
    }

    // acc[0..11]  : m-tile0 (rows w0..w0+15),  n8 tile j  (u0 = w0 + 8j)
    // acc[12..23] : m-tile1 (rows w0+16..+31), n8 tile j+2
    float acc[24][4];
#pragma unroll
    for (int n = 0; n < 24; ++n)
#pragma unroll
        for (int i = 0; i < 4; ++i) acc[n][i] = 0.0f;

    // compute constants
    const int w0 = wid * 32;
    const int b_rowoff = (lane & 7) + ((lane >> 4) & 1) * 8;
    const int b_k16 = ((lane >> 3) & 1) * 16;
    const int ad_w = w0 + (lane >> 2);
    const int ad_k = (lane & 3) * 2;

    // issue all cp.async for chunk ch into ring slot ch%3 (8 ops/thread)
    auto issue = [&](int ch) {
        const int c0 = ch * KC;
        const uint32_t stA = base_u + (ch % 3) * STPAIR;
        const uint32_t stB = stA + STBYTES;
#pragma unroll
        for (int j = 0; j < 8; ++j) {
            int op = tid + j * NTHREADS;        // 0..1535
            const bool isA = (op < 768);
            if (!isA) op -= 768;
            const int k = op / 48, q = op % 48;
            const uint32_t dst = (isA ? stA : stB) + k * (STROWF * 4) + q * 16;
            const float* src = (isA ? a_src : b_src) + (size_t)(c0 + k) * HWn + 4 * q;
            cp_async16(dst, src);
        }
        asm volatile("cp.async.commit_group;" ::: "memory");
    };

    uint32_t AH[2][4], AL[2][4];   // A fragments (2 m16 tiles) for next compute

    issue(0);
    issue(1);
    asm volatile("cp.async.wait_group 1;" ::: "memory");   // chunk 0 complete
    __syncthreads();   // stage(0) + tile pad zeros visible

    for (int i = 0; i < NCHUNK; ++i) {
        const int s3 = i % 3;
        if (i + 2 < NCHUNK) issue(i + 2);

        // ---- convert B(i): stageB[ring s3] -> tileB[i&1] (544 tasks) ----
        {
            const char* sb = smp + s3 * STPAIR + STBYTES;
            char* tbp = smp + ((i & 1) ? OFF_TB1 : OFF_TB0);
            for (int t = tid; t < BROWS * 2; t += NTHREADS) {
                const int u = t % BROWS;
                const int g = t / BROWS;
                const int col = u - PADn;
                if (col >= 0 && col < Wn) {
                    float v[8];
#pragma unroll
                    for (int j = 0; j < 8; ++j)
                        v[j] = *(const float*)(sb + (8 * g + j) * (STROWF * 4) + 4 * col);
                    unsigned hu[4], lu[4];
#pragma unroll
                    for (int k = 0; k < 4; ++k) {
                        __nv_bfloat162 hh = __floats2bfloat162_rn(v[2 * k], v[2 * k + 1]);
                        const float r0 = v[2 * k] - __bfloat162float(hh.x);
                        const float r1 = v[2 * k + 1] - __bfloat162float(hh.y);
                        __nv_bfloat162 ll = __floats2bfloat162_rn(r0, r1);
                        hu[k] = *(unsigned*)&hh;
                        lu[k] = *(unsigned*)&ll;
                    }
                    char* rowp = tbp + u * ROWB;
                    *(uint4*)(rowp + SWX(u, 16 * g)) = make_uint4(hu[0], hu[1], hu[2], hu[3]);
                    *(uint4*)(rowp + SWX(u, 32 + 16 * g)) = make_uint4(lu[0], lu[1], lu[2], lu[3]);
                }
            }
        }

        // ---- compute chunk i-1 from tileB[(i-1)&1]: 7 LDSM pairs, 24 tile-MMAs ----
        if (i > 0) {
            const uint32_t tb = base_u + (((i - 1) & 1) ? OFF_TB1 : OFF_TB0);
#pragma unroll
            for (int ntp = 0; ntp < 7; ++ntp) {
                const int ub = w0 + ntp * 16 + b_rowoff;
                uint32_t bh[4], bl[4];
                LDSM_X4(bh, tb + ub * ROWB + SWX(ub, b_k16));
                LDSM_X4(bl, tb + ub * ROWB + SWX(ub, 32 + b_k16));
#pragma unroll
                for (int t2 = 0; t2 < 2; ++t2) {
                    const int tj = ntp * 2 + t2;   // global n8 tile 0..13
                    const uint32_t b0h = bh[2 * t2], b1h = bh[2 * t2 + 1];
                    const uint32_t b0l = bl[2 * t2], b1l = bl[2 * t2 + 1];
                    if (tj < 12) {                 // m-tile 0
                        float* a4 = acc[tj];
                        MMA_BF16(a4, AH[0], b0h, b1h);
                        MMA_BF16(a4, AH[0], b0l, b1l);
                        MMA_BF16(a4, AL[0], b0h, b1h);
                    }
                    if (tj >= 2) {                 // m-tile 1
                        float* a4 = acc[12 + tj - 2];
                        MMA_BF16(a4, AH[1], b0h, b1h);
                        MMA_BF16(a4, AH[1], b0l, b1l);
                        MMA_BF16(a4, AL[1], b0h, b1h);
                    }
                }
            }
        }

        // ---- build A fragments (both m16 tiles) for chunk i from stageA[s3] ----
        {
            const char* sa = smp + s3 * STPAIR;
#pragma unroll
            for (int mt = 0; mt < 2; ++mt) {
#pragma unroll
                for (int q = 0; q < 4; ++q) {
                    const int ww = ad_w + 16 * mt + (q & 1) * 8;
                    const int kk = ad_k + (q >> 1) * 8;
                    const float f0 = *(const float*)(sa + kk * (STROWF * 4) + 4 * ww);
                    const float f1 = *(const float*)(sa + (kk + 1) * (STROWF * 4) + 4 * ww);
                    __nv_bfloat162 hh = __floats2bfloat162_rn(f0, f1);
                    const float r0 = f0 - __bfloat162float(hh.x);
                    const float r1 = f1 - __bfloat162float(hh.y);
                    __nv_bfloat162 ll = __floats2bfloat162_rn(r0, r1);
                    AH[mt][q] = *(uint32_t*)&hh;
                    AL[mt][q] = *(uint32_t*)&ll;
                }
            }
        }

        if (i + 2 < NCHUNK) {
            asm volatile("cp.async.wait_group 1;" ::: "memory");
        } else {
            asm volatile("cp.async.wait_group 0;" ::: "memory");
        }
        __syncthreads();
    }

    // ---- tail: compute chunk NCHUNK-1 ----
    {
        const uint32_t tb = base_u + (((NCHUNK - 1) & 1) ? OFF_TB1 : OFF_TB0);
#pragma unroll
        for (int ntp = 0; ntp < 7; ++ntp) {
            const int ub = w0 + ntp * 16 + b_rowoff;
            uint32_t bh[4], bl[4];
            LDSM_X4(bh, tb + ub * ROWB + SWX(ub, b_k16));
            LDSM_X4(bl, tb + ub * ROWB + SWX(ub, 32 + b_k16));
#pragma unroll
            for (int t2 = 0; t2 < 2; ++t2) {
                const int tj = ntp * 2 + t2;
                const uint32_t b0h = bh[2 * t2], b1h = bh[2 * t2 + 1];
                const uint32_t b0l = bl[2 * t2], b1l = bl[2 * t2 + 1];
                if (tj < 12) {
                    float* a4 = acc[tj];
                    MMA_BF16(a4, AH[0], b0h, b1h);
                    MMA_BF16(a4, AH[0], b0l, b1l);
                    MMA_BF16(a4, AL[0], b0h, b1h);
                }
                if (tj >= 2) {
                    float* a4 = acc[12 + tj - 2];
                    MMA_BF16(a4, AH[1], b0h, b1h);
                    MMA_BF16(a4, AH[1], b0l, b1l);
                    MMA_BF16(a4, AL[1], b0h, b1h);
                }
            }
        }
    }
    __syncthreads();

    // ---- epilogue: band extraction into smem, then coalesced store ----
    float* outT = (float*)smp;  // [81][192] f32
    const float scale = 1.0f / (float)Cn;
    const int r_ = lane >> 2;
    const int col2 = (lane & 3) * 2;
#pragma unroll
    for (int ai = 0; ai < 24; ++ai) {
        const int mt = ai / 12;
        const int tg = (ai % 12) + 2 * mt;    // global n8 tile index
#pragma unroll
        for (int half = 0; half < 2; ++half) {
            const int mrow = 16 * mt + r_ + half * 8;
            const int w = w0 + mrow;
#pragma unroll
            for (int e = 0; e < 2; ++e) {
                const int d = 8 * tg + col2 + e - mrow;
                if (d >= 0 && d < Dn) {
                    outT[d * Wn + w] = acc[ai][half * 2 + e] * scale;
                }
            }
        }
    }
    __syncthreads();

    for (int t = tid; t < Dn * (Wn / 4); t += NTHREADS) {
        const int d = t / (Wn / 4);
        const int q = t % (Wn / 4);
        const float4 v = ((const float4*)outT)[d * (Wn / 4) + q];
        *(float4*)(out + (((size_t)b * Dn + d) * Hn + h) * Wn + q * 4) = v;
    }
}

extern "C" void kernel_launch(void* const* d_in, const int* in_sizes, int n_in,
                              void* d_out, int out_size) {
    const float* in1 = (const float*)d_in[0];
    const float* in2 = (const float*)d_in[1];
    float* out = (float*)d_out;
    cudaFuncSetAttribute(corr1d_m32_kernel, cudaFuncAttributeMaxDynamicSharedMemorySize, DYNSMEM);
    dim3 grid(Hn, Bn);   // (96, 8)
    corr1d_m32_kernel<<<grid, NTHREADS, DYNSMEM>>>(in1, in2, out);
}

// round 12
// speedup vs baseline: 1.1917x; 1.0348x over previous
#include <cuda_runtime.h>
#include <cuda_bf16.h>
#include <cstdint>

// Correlation1D band-GEMM: k16 bf16 3-pass fp32 emulation.
// R12 = R11 (m32 warps, 3-slot cp.async ring, A-direct, 1 sync/chunk) with all
// per-chunk integer div/mod strength-reduced to startup constants + adds.
// out[b,d,h,w] = (1/256)*sum_c in1[b,c,h,w]*in2pad[b,c,h,w+d-40]

#define Bn 8
#define Cn 256
#define Hn 96
#define Wn 192
#define Dn 81
#define PADn 40
#define HWn (Hn * Wn)

#define NTHREADS 192
#define KC 16
#define NCHUNK (Cn / KC)          // 16
#define BROWS 272

#define STROWF 196                // fp32 stage row floats (192 used, pad for banks)
#define STROWB (STROWF * 4)       // 784
#define STBYTES (KC * STROWB)     // 12544
#define STPAIR (2 * STBYTES)      // 25088

#define ROWB 64                   // tileB row: [hi 16ch = 32B | lo 32B]
#define TBB (BROWS * ROWB)        // 17408

#define OFF_TB0 (3 * STPAIR)                // 75264
#define OFF_TB1 (OFF_TB0 + TBB)             // 92672
#define SMEM_USED (OFF_TB1 + TBB)           // 110080
#define DYNSMEM (SMEM_USED + 1024)

#define SWX(row, koff) ((unsigned)(koff) ^ ((((unsigned)(row) >> 1) & 3u) << 4))

static __device__ __forceinline__ uint32_t smem_u32(const void* p) {
    uint32_t a;
    asm("{ .reg .u64 t; cvta.to.shared.u64 t, %1; cvt.u32.u64 %0, t; }" : "=r"(a) : "l"(p));
    return a;
}

static __device__ __forceinline__ void cp_async16(uint32_t dst, const void* src) {
    asm volatile("cp.async.cg.shared.global [%0], [%1], 16;" :: "r"(dst), "l"(src) : "memory");
}

#define MMA_BF16(a4, A, b0, b1)                                                \
    asm volatile("mma.sync.aligned.m16n8k16.row.col.f32.bf16.bf16.f32 "        \
        "{%0,%1,%2,%3}, {%4,%5,%6,%7}, {%8,%9}, {%0,%1,%2,%3};"                \
        : "+f"((a4)[0]), "+f"((a4)[1]), "+f"((a4)[2]), "+f"((a4)[3])           \
        : "r"((A)[0]), "r"((A)[1]), "r"((A)[2]), "r"((A)[3]), "r"(b0), "r"(b1))

#define LDSM_X4(r, addr)                                                       \
    asm volatile("ldmatrix.sync.aligned.m8n8.x4.shared.b16 {%0,%1,%2,%3}, [%4];" \
        : "=r"((r)[0]), "=r"((r)[1]), "=r"((r)[2]), "=r"((r)[3]) : "r"(addr))

__global__ __launch_bounds__(NTHREADS, 2)
void corr1d_sr_kernel(const float* __restrict__ in1,
                      const float* __restrict__ in2,
                      float* __restrict__ out) {
    extern __shared__ char dsm_raw[];
    const uint32_t dsm_addr = smem_u32(dsm_raw);
    const uint32_t base_u = (dsm_addr + 1023u) & ~1023u;
    char* smp = dsm_raw + (base_u - dsm_addr);

    const int h = blockIdx.x;
    const int b = blockIdx.y;
    const int tid = threadIdx.x;
    const int wid = tid >> 5;
    const int lane = tid & 31;

    const float* a_src = in1 + (size_t)b * Cn * HWn + (size_t)h * Wn;
    const float* b_src = in2 + (size_t)b * Cn * HWn + (size_t)h * Wn;

    // ---- cp.async per-thread constants: q fixed, k = krow + 4j ----
    const int iq16 = (tid % 48) * 16;      // byte offset within a stage row
    const int ikr = tid / 48;              // 0..3
    const uint32_t dstoff = (uint32_t)(ikr * STROWB + iq16);
    const float* a_tsrc = a_src + (size_t)ikr * HWn + (iq16 >> 2);
    const float* b_tsrc = b_src + (size_t)ikr * HWn + (iq16 >> 2);

    // ---- convert per-thread static tasks (u, g, col, valid) ----
    const int cu0 = tid, cg0 = 0, cc0 = tid - PADn;
    const bool cv0 = (tid >= PADn);
    const int cu1 = (tid < 80) ? (tid + 192) : (tid - 80);
    const int cg1 = (tid < 80) ? 0 : 1;
    const int cc1 = (tid < 80) ? (tid + 152) : (tid - 120);
    const bool cv1 = (tid < 40) || (tid >= 120);
    const int cu2 = tid + 112, cg2 = 1, cc2 = tid + 72;
    const bool cv2 = (tid < 120);

    // ---- zero tileB pad rows (u<40, u>=232) in both buffers, once ----
    for (int t = tid; t < 2 * 80 * 4; t += NTHREADS) {
        const int buf = t / 320;
        const int r = (t % 320) / 4;
        const int j = t % 4;
        const int u = (r < 40) ? r : (232 + r - 40);
        ((uint4*)(smp + (buf ? OFF_TB1 : OFF_TB0) + u * ROWB))[j] = make_uint4(0, 0, 0, 0);
    }

    float acc[24][4];
#pragma unroll
    for (int n = 0; n < 24; ++n)
#pragma unroll
        for (int i = 0; i < 4; ++i) acc[n][i] = 0.0f;

    // compute constants
    const int w0 = wid * 32;
    const int b_rowoff = (lane & 7) + ((lane >> 4) & 1) * 8;
    const int b_k16 = ((lane >> 3) & 1) * 16;
    const int ad_w = w0 + (lane >> 2);
    const int ad_k = (lane & 3) * 2;

    // issue all cp.async for chunk ch into ring slot ch%3 (8 ops/thread, no div)
    auto issue = [&](int ch, int s3) {
        const uint32_t stA = base_u + (uint32_t)s3 * STPAIR + dstoff;
        const uint32_t stB = stA + STBYTES;
        const size_t co = (size_t)ch * KC * HWn;
        const float* pa = a_tsrc + co;
        const float* pb = b_tsrc + co;
#pragma unroll
        for (int j = 0; j < 4; ++j) {
            cp_async16(stA + j * (4 * STROWB), pa + (size_t)(4 * j) * HWn);
            cp_async16(stB + j * (4 * STROWB), pb + (size_t)(4 * j) * HWn);
        }
        asm volatile("cp.async.commit_group;" ::: "memory");
    };

    // one convert task: stageB[slot] -> tileB row u
    auto cvtask = [&](const char* sb, char* tbp, int u, int g, int col, bool valid) {
        if (!valid) return;
        float v[8];
#pragma unroll
        for (int j = 0; j < 8; ++j)
            v[j] = *(const float*)(sb + (8 * g + j) * STROWB + 4 * col);
        unsigned hu[4], lu[4];
#pragma unroll
        for (int k = 0; k < 4; ++k) {
            __nv_bfloat162 hh = __floats2bfloat162_rn(v[2 * k], v[2 * k + 1]);
            const float r0 = v[2 * k] - __bfloat162float(hh.x);
            const float r1 = v[2 * k + 1] - __bfloat162float(hh.y);
            __nv_bfloat162 ll = __floats2bfloat162_rn(r0, r1);
            hu[k] = *(unsigned*)&hh;
            lu[k] = *(unsigned*)&ll;
        }
        char* rowp = tbp + u * ROWB;
        *(uint4*)(rowp + SWX(u, 16 * g)) = make_uint4(hu[0], hu[1], hu[2], hu[3]);
        *(uint4*)(rowp + SWX(u, 32 + 16 * g)) = make_uint4(lu[0], lu[1], lu[2], lu[3]);
    };

    uint32_t AH[2][4], AL[2][4];

    issue(0, 0);
    issue(1, 1);
    asm volatile("cp.async.wait_group 1;" ::: "memory");
    __syncthreads();

    int s3 = 0, s3n = 2;   // current ring slot; slot for chunk i+2
    for (int i = 0; i < NCHUNK; ++i) {
        if (i + 2 < NCHUNK) issue(i + 2, s3n);

        // ---- convert B(i): stageB[s3] -> tileB[i&1], 3 static tasks ----
        {
            const char* sb = smp + s3 * STPAIR + STBYTES;
            char* tbp = smp + ((i & 1) ? OFF_TB1 : OFF_TB0);
            cvtask(sb, tbp, cu0, cg0, cc0, cv0);
            cvtask(sb, tbp, cu1, cg1, cc1, cv1);
            cvtask(sb, tbp, cu2, cg2, cc2, cv2);
        }

        // ---- compute chunk i-1 from tileB[(i-1)&1] ----
        if (i > 0) {
            const uint32_t tb = base_u + (((i - 1) & 1) ? OFF_TB1 : OFF_TB0);
#pragma unroll
            for (int ntp = 0; ntp < 7; ++ntp) {
                const int ub = w0 + ntp * 16 + b_rowoff;
                uint32_t bh[4], bl[4];
                LDSM_X4(bh, tb + ub * ROWB + SWX(ub, b_k16));
                LDSM_X4(bl, tb + ub * ROWB + SWX(ub, 32 + b_k16));
#pragma unroll
                for (int t2 = 0; t2 < 2; ++t2) {
                    const int tj = ntp * 2 + t2;
                    const uint32_t b0h = bh[2 * t2], b1h = bh[2 * t2 + 1];
                    const uint32_t b0l = bl[2 * t2], b1l = bl[2 * t2 + 1];
                    if (tj < 12) {
                        float* a4 = acc[tj];
                        MMA_BF16(a4, AH[0], b0h, b1h);
                        MMA_BF16(a4, AH[0], b0l, b1l);
                        MMA_BF16(a4, AL[0], b0h, b1h);
                    }
                    if (tj >= 2) {
                        float* a4 = acc[12 + tj - 2];
                        MMA_BF16(a4, AH[1], b0h, b1h);
                        MMA_BF16(a4, AH[1], b0l, b1l);
                        MMA_BF16(a4, AL[1], b0h, b1h);
                    }
                }
            }
        }

        // ---- build A fragments for chunk i from stageA[s3] ----
        {
            const char* sa = smp + s3 * STPAIR;
#pragma unroll
            for (int mt = 0; mt < 2; ++mt) {
#pragma unroll
                for (int q = 0; q < 4; ++q) {
                    const int ww = ad_w + 16 * mt + (q & 1) * 8;
                    const int kk = ad_k + (q >> 1) * 8;
                    const float f0 = *(const float*)(sa + kk * STROWB + 4 * ww);
                    const float f1 = *(const float*)(sa + (kk + 1) * STROWB + 4 * ww);
                    __nv_bfloat162 hh = __floats2bfloat162_rn(f0, f1);
                    const float r0 = f0 - __bfloat162float(hh.x);
                    const float r1 = f1 - __bfloat162float(hh.y);
                    __nv_bfloat162 ll = __floats2bfloat162_rn(r0, r1);
                    AH[mt][q] = *(uint32_t*)&hh;
                    AL[mt][q] = *(uint32_t*)&ll;
                }
            }
        }

        if (i + 2 < NCHUNK) {
            asm volatile("cp.async.wait_group 1;" ::: "memory");
        } else {
            asm volatile("cp.async.wait_group 0;" ::: "memory");
        }
        __syncthreads();

        s3 = (s3 == 2) ? 0 : s3 + 1;
        s3n = (s3n == 2) ? 0 : s3n + 1;
    }

    // ---- tail: compute chunk NCHUNK-1 ----
    {
        const uint32_t tb = base_u + (((NCHUNK - 1) & 1) ? OFF_TB1 : OFF_TB0);
#pragma unroll
        for (int ntp = 0; ntp < 7; ++ntp) {
            const int ub = w0 + ntp * 16 + b_rowoff;
            uint32_t bh[4], bl[4];
            LDSM_X4(bh, tb + ub * ROWB + SWX(ub, b_k16));
            LDSM_X4(bl, tb + ub * ROWB + SWX(ub, 32 + b_k16));
#pragma unroll
            for (int t2 = 0; t2 < 2; ++t2) {
                const int tj = ntp * 2 + t2;
                const uint32_t b0h = bh[2 * t2], b1h = bh[2 * t2 + 1];
                const uint32_t b0l = bl[2 * t2], b1l = bl[2 * t2 + 1];
                if (tj < 12) {
                    float* a4 = acc[tj];
                    MMA_BF16(a4, AH[0], b0h, b1h);
                    MMA_BF16(a4, AH[0], b0l, b1l);
                    MMA_BF16(a4, AL[0], b0h, b1h);
                }
                if (tj >= 2) {
                    float* a4 = acc[12 + tj - 2];
                    MMA_BF16(a4, AH[1], b0h, b1h);
                    MMA_BF16(a4, AH[1], b0l, b1l);
                    MMA_BF16(a4, AL[1], b0h, b1h);
                }
            }
        }
    }
    __syncthreads();

    // ---- epilogue: band extraction into smem, then coalesced store ----
    float* outT = (float*)smp;  // [81][192] f32
    const float scale = 1.0f / (float)Cn;
    const int r_ = lane >> 2;
    const int col2 = (lane & 3) * 2;
#pragma unroll
    for (int ai = 0; ai < 24; ++ai) {
        const int mt = ai / 12;
        const int tg = (ai % 12) + 2 * mt;
#pragma unroll
        for (int half = 0; half < 2; ++half) {
            const int mrow = 16 * mt + r_ + half * 8;
            const int w = w0 + mrow;
#pragma unroll
            for (int e = 0; e < 2; ++e) {
                const int d = 8 * tg + col2 + e - mrow;
                if (d >= 0 && d < Dn) {
                    outT[d * Wn + w] = acc[ai][half * 2 + e] * scale;
                }
            }
        }
    }
    __syncthreads();

    for (int t = tid; t < Dn * (Wn / 4); t += NTHREADS) {
        const int d = t / (Wn / 4);
        const int q = t % (Wn / 4);
        const float4 v = ((const float4*)outT)[d * (Wn / 4) + q];
        *(float4*)(out + (((size_t)b * Dn + d) * Hn + h) * Wn + q * 4) = v;
    }
}

extern "C" void kernel_launch(void* const* d_in, const int* in_sizes, int n_in,
                              void* d_out, int out_size) {
    const float* in1 = (const float*)d_in[0];
    const float* in2 = (const float*)d_in[1];
    float* out = (float*)d_out;
    cudaFuncSetAttribute(corr1d_sr_kernel, cudaFuncAttributeMaxDynamicSharedMemorySize, DYNSMEM);
    dim3 grid(Hn, Bn);   // (96, 8)
    corr1d_sr_kernel<<<grid, NTHREADS, DYNSMEM>>>(in1, in2, out);
}